// round 6
// baseline (speedup 1.0000x reference)
#include <cuda_runtime.h>
#include <cstdint>

// Problem constants (fixed by the reference)
#define NU  100000
#define NI  40000
#define NN  140000            // NU + NI
#define H   32
#define IND 128
#define NE  1200000
#define NDIR (2 * NE)         // directed edges (both orientations)

#define SCAN_T 256
#define SCAN_B ((NN + SCAN_T - 1) / SCAN_T)   // 547

// Packed CSR entry: neighbor id + edge weight (8 bytes, one LDG.64)
struct __align__(8) Ent { int n; float w; };

// Scratch: device globals (allocation-free contract).
__device__ float g_x0[(size_t)NN * H];   // projection output
__device__ float g_x1[(size_t)NN * H];   // layer-1 output
__device__ int   g_deg[NN];
__device__ float g_dinv[NN];
__device__ int   g_off[NN + 1];          // CSR row offsets
__device__ int   g_cur[NN];              // build cursors
__device__ Ent   g_ent[NDIR];            // packed CSR (neighbor, weight)
__device__ int   g_bsum[SCAN_B];         // per-block degree sums
__device__ int   g_bbase[SCAN_B];        // exclusive block bases

// ---------------------------------------------------------------------------
__global__ void k_zero_deg() {
    int t = blockIdx.x * blockDim.x + threadIdx.x;
    if (t < NN) g_deg[t] = 0;
}

// Degree count (matches segment_sum(ones, dst), symmetric bipartite edges)
__global__ void k_count_deg(const int* __restrict__ eu, const int* __restrict__ ei) {
    int t = blockIdx.x * blockDim.x + threadIdx.x;
    if (t < NE) {
        atomicAdd(&g_deg[eu[t]], 1);
        atomicAdd(&g_deg[NU + ei[t]], 1);
    }
}

// ---------------------------------------------------------------------------
// 3-phase grid-wide exclusive scan of g_deg -> g_off (+ cursors).
// p1 also computes g_dinv (fused — it loads deg anyway).
// ---------------------------------------------------------------------------
__global__ void k_scan_p1() {
    __shared__ int sh[SCAN_T];
    const int i = blockIdx.x * SCAN_T + threadIdx.x;
    int d0 = 0;
    if (i < NN) {
        d0 = g_deg[i];
        g_dinv[i] = (d0 > 0) ? rsqrtf((float)d0) : 0.0f;
    }
    sh[threadIdx.x] = d0;
    __syncthreads();
    for (int d = SCAN_T / 2; d > 0; d >>= 1) {
        if (threadIdx.x < d) sh[threadIdx.x] += sh[threadIdx.x + d];
        __syncthreads();
    }
    if (threadIdx.x == 0) g_bsum[blockIdx.x] = sh[0];
}

__global__ void k_scan_p2() {
    __shared__ int sh[1024];
    const int tid = threadIdx.x;
    const int v = (tid < SCAN_B) ? g_bsum[tid] : 0;
    sh[tid] = v;
    __syncthreads();
    for (int d = 1; d < 1024; d <<= 1) {
        int t = (tid >= d) ? sh[tid - d] : 0;
        __syncthreads();
        sh[tid] += t;
        __syncthreads();
    }
    if (tid < SCAN_B) g_bbase[tid] = sh[tid] - v;   // exclusive base
}

__global__ void k_scan_p3() {
    __shared__ int sh[SCAN_T];
    const int i = blockIdx.x * SCAN_T + threadIdx.x;
    const int v = (i < NN) ? g_deg[i] : 0;
    sh[threadIdx.x] = v;
    __syncthreads();
    for (int d = 1; d < SCAN_T; d <<= 1) {
        int t = (threadIdx.x >= d) ? sh[threadIdx.x - d] : 0;
        __syncthreads();
        sh[threadIdx.x] += t;
        __syncthreads();
    }
    const int incl = sh[threadIdx.x];
    const int base = g_bbase[blockIdx.x];
    if (i < NN) {
        const int off = base + incl - v;            // exclusive
        g_off[i] = off;
        g_cur[i] = off;
    }
    if (i == NN - 1) g_off[NN] = base + incl;       // == 2*NE
}

// ---------------------------------------------------------------------------
// CSR build: each undirected edge (u, i) inserts both directions.
// ---------------------------------------------------------------------------
__global__ void k_build(const int* __restrict__ eu, const int* __restrict__ ei) {
    int t = blockIdx.x * blockDim.x + threadIdx.x;
    if (t < NE) {
        const int u  = eu[t];
        const int it = NU + ei[t];
        const float w = g_dinv[u] * g_dinv[it];
        int pu = atomicAdd(&g_cur[u], 1);
        g_ent[pu] = Ent{it, w};
        int pi = atomicAdd(&g_cur[it], 1);
        g_ent[pi] = Ent{u, w};
    }
}

// ---------------------------------------------------------------------------
// TypeProjector v2: register-tiled GEMM, out = x[rows,128] @ W[128,32] + b.
// Block: 256 threads, tile 256 rows x 32 cols. Thread: 8 rows x 4 cols.
// x read straight from gmem (each 16B chunk hits one warp, lane-broadcast);
// W transposed+padded in shared (conflict-free LDS.128).
// LDS/FMA ~ 1:10 -> FMA-bound (~33us total) instead of LDS-crossbar-bound.
// ---------------------------------------------------------------------------
#define PT_ROWS 256
__global__ void __launch_bounds__(256) k_project2(
        const float* __restrict__ x, const float* __restrict__ Wm,
        const float* __restrict__ b, int row_offset, int rows) {
    __shared__ float WsT[32 * 132];     // [col][k], stride 132 (pad: no conflicts)

    const int tid = threadIdx.x;
    // Stage W transposed: Wm is [k][col] row-major.
    for (int i = tid; i < IND * H; i += 256) {
        const int k = i >> 5, c = i & 31;
        WsT[c * 132 + k] = Wm[i];
    }
    __syncthreads();

    const int colg = tid & 7;            // 8 col-groups x 4 cols
    const int rowg = tid >> 3;           // 32 row-groups x 8 rows
    const int col0 = colg * 4;
    const int row0 = blockIdx.x * PT_ROWS + rowg * 8;

    float acc[8][4];
    #pragma unroll
    for (int r = 0; r < 8; r++)
        #pragma unroll
        for (int c = 0; c < 4; c++) acc[r][c] = 0.0f;

    for (int k4 = 0; k4 < IND / 4; k4++) {
        // W chunk: 4 cols x 4 k-values
        float4 w4[4];
        #pragma unroll
        for (int c = 0; c < 4; c++)
            w4[c] = *reinterpret_cast<const float4*>(&WsT[(col0 + c) * 132 + k4 * 4]);

        // x chunk: 8 rows x 4 k-values (gmem; lanes with same rowg broadcast)
        #pragma unroll
        for (int r = 0; r < 8; r++) {
            const int row = row0 + r;
            float4 x4 = (row < rows)
                ? *reinterpret_cast<const float4*>(x + (size_t)row * IND + k4 * 4)
                : make_float4(0.f, 0.f, 0.f, 0.f);
            #pragma unroll
            for (int c = 0; c < 4; c++) {
                acc[r][c] = fmaf(x4.x, w4[c].x, acc[r][c]);
                acc[r][c] = fmaf(x4.y, w4[c].y, acc[r][c]);
                acc[r][c] = fmaf(x4.z, w4[c].z, acc[r][c]);
                acc[r][c] = fmaf(x4.w, w4[c].w, acc[r][c]);
            }
        }
    }

    const float4 b4 = *reinterpret_cast<const float4*>(b + col0);
    #pragma unroll
    for (int r = 0; r < 8; r++) {
        const int row = row0 + r;
        if (row < rows) {
            float4 o = make_float4(acc[r][0] + b4.x, acc[r][1] + b4.y,
                                   acc[r][2] + b4.z, acc[r][3] + b4.w);
            *reinterpret_cast<float4*>(&g_x0[(size_t)(row_offset + row) * H + col0]) = o;
        }
    }
}

// ---------------------------------------------------------------------------
// Gather body: acc = sum_{j in [s,e)} ent[j].w * xin[ent[j].n * H + lane].
// 8-way unroll -> MLP ~8 on the random 128B row loads (L2-resident).
// ---------------------------------------------------------------------------
__device__ __forceinline__ float gather_row(const float* __restrict__ xin,
                                            int s, int e, int lane) {
    float acc = 0.0f;
    int j = s;
    for (; j + 8 <= e; j += 8) {
        Ent t0 = g_ent[j],     t1 = g_ent[j + 1];
        Ent t2 = g_ent[j + 2], t3 = g_ent[j + 3];
        Ent t4 = g_ent[j + 4], t5 = g_ent[j + 5];
        Ent t6 = g_ent[j + 6], t7 = g_ent[j + 7];
        const float v0 = xin[(size_t)t0.n * H + lane];
        const float v1 = xin[(size_t)t1.n * H + lane];
        const float v2 = xin[(size_t)t2.n * H + lane];
        const float v3 = xin[(size_t)t3.n * H + lane];
        const float v4 = xin[(size_t)t4.n * H + lane];
        const float v5 = xin[(size_t)t5.n * H + lane];
        const float v6 = xin[(size_t)t6.n * H + lane];
        const float v7 = xin[(size_t)t7.n * H + lane];
        acc = fmaf(t0.w, v0, acc); acc = fmaf(t1.w, v1, acc);
        acc = fmaf(t2.w, v2, acc); acc = fmaf(t3.w, v3, acc);
        acc = fmaf(t4.w, v4, acc); acc = fmaf(t5.w, v5, acc);
        acc = fmaf(t6.w, v6, acc); acc = fmaf(t7.w, v7, acc);
    }
    for (; j < e; j++) {
        Ent t = g_ent[j];
        acc = fmaf(t.w, xin[(size_t)t.n * H + lane], acc);
    }
    return acc;
}

// Layer 1: x1[v] = sum_{n in N(v)} w * x0[n]. One warp per node, lane = column.
__global__ void __launch_bounds__(256) k_gather1() {
    const int v = blockIdx.x * (blockDim.x >> 5) + (threadIdx.x >> 5);
    if (v >= NN) return;
    const int lane = threadIdx.x & 31;
    const float acc = gather_row(g_x0, g_off[v], g_off[v + 1], lane);
    g_x1[(size_t)v * H + lane] = acc;
}

// Layer 2 + fused mean epilogue: out[v] = (x0[v] + x1[v] + gather(x1))/3.
__global__ void __launch_bounds__(256) k_gather2(float* __restrict__ out) {
    const int v = blockIdx.x * (blockDim.x >> 5) + (threadIdx.x >> 5);
    if (v >= NN) return;
    const int lane = threadIdx.x & 31;
    const float acc = gather_row(g_x1, g_off[v], g_off[v + 1], lane);
    const size_t idx = (size_t)v * H + lane;
    out[idx] = (g_x0[idx] + g_x1[idx] + acc) * (1.0f / 3.0f);
}

extern "C" void kernel_launch(void* const* d_in, const int* in_sizes, int n_in,
                              void* d_out, int out_size) {
    const float* x_user = (const float*)d_in[0];
    const float* x_item = (const float*)d_in[1];
    const int*   eu     = (const int*)  d_in[2];
    const int*   ei     = (const int*)  d_in[3];
    const float* Wu     = (const float*)d_in[4];
    const float* bu     = (const float*)d_in[5];
    const float* Wi     = (const float*)d_in[6];
    const float* bi     = (const float*)d_in[7];
    float* out = (float*)d_out;

    const int B = 256;

    // Launch order puts k_project2 (users) at launch idx 3 -> ncu captures it.
    k_zero_deg<<<(NN + B - 1) / B, B>>>();                       // 0
    k_count_deg<<<(NE + B - 1) / B, B>>>(eu, ei);                // 1
    k_scan_p1<<<SCAN_B, SCAN_T>>>();                             // 2 (+dinv)
    k_project2<<<(NU + PT_ROWS - 1) / PT_ROWS, 256>>>(x_user, Wu, bu, 0,  NU);  // 3 <- profiled
    k_project2<<<(NI + PT_ROWS - 1) / PT_ROWS, 256>>>(x_item, Wi, bi, NU, NI);  // 4
    k_scan_p2<<<1, 1024>>>();                                    // 5
    k_scan_p3<<<SCAN_B, SCAN_T>>>();                             // 6
    k_build<<<(NE + B - 1) / B, B>>>(eu, ei);                    // 7

    const int warps_per_block = B / 32;
    const int gather_blocks = (NN + warps_per_block - 1) / warps_per_block;
    k_gather1<<<gather_blocks, B>>>();                           // 8
    k_gather2<<<gather_blocks, B>>>(out);                        // 9
}

// round 16
// speedup vs baseline: 1.5075x; 1.5075x over previous
#include <cuda_runtime.h>
#include <cstdint>

// Problem constants (fixed by the reference)
#define NU  100000
#define NI  40000
#define NN  140000            // NU + NI
#define H   32
#define IND 128
#define NE  1200000
#define NDIR (2 * NE)         // directed edges (both orientations)

#define SCAN_T 256
#define SCAN_B ((NN + SCAN_T - 1) / SCAN_T)   // 547

// Packed CSR entry: neighbor id + edge weight (8 bytes, one LDG.64)
struct __align__(8) Ent { int n; float w; };

// Scratch: device globals (allocation-free contract).
__device__ float g_x0[(size_t)NN * H];   // projection output
__device__ float g_x1[(size_t)NN * H];   // layer-1 output
__device__ int   g_deg[NN];
__device__ float g_dinv[NN];
__device__ int   g_off[NN + 1];          // CSR row offsets
__device__ int   g_cur[NN];              // build cursors
__device__ Ent   g_ent[NDIR];            // packed CSR (neighbor, weight)
__device__ int   g_bsum[SCAN_B];         // per-block degree sums
__device__ int   g_bbase[SCAN_B];        // exclusive block bases

// ---------------------------------------------------------------------------
__global__ void k_zero_deg() {
    int t = blockIdx.x * blockDim.x + threadIdx.x;
    if (t < NN) g_deg[t] = 0;
}

// Degree count (matches segment_sum(ones, dst), symmetric bipartite edges)
__global__ void k_count_deg(const int* __restrict__ eu, const int* __restrict__ ei) {
    int t = blockIdx.x * blockDim.x + threadIdx.x;
    if (t < NE) {
        atomicAdd(&g_deg[eu[t]], 1);
        atomicAdd(&g_deg[NU + ei[t]], 1);
    }
}

// ---------------------------------------------------------------------------
// 3-phase grid-wide exclusive scan of g_deg -> g_off (+ cursors).
// p1 also computes g_dinv (fused — it loads deg anyway).
// ---------------------------------------------------------------------------
__global__ void k_scan_p1() {
    __shared__ int sh[SCAN_T];
    const int i = blockIdx.x * SCAN_T + threadIdx.x;
    int d0 = 0;
    if (i < NN) {
        d0 = g_deg[i];
        g_dinv[i] = (d0 > 0) ? rsqrtf((float)d0) : 0.0f;
    }
    sh[threadIdx.x] = d0;
    __syncthreads();
    for (int d = SCAN_T / 2; d > 0; d >>= 1) {
        if (threadIdx.x < d) sh[threadIdx.x] += sh[threadIdx.x + d];
        __syncthreads();
    }
    if (threadIdx.x == 0) g_bsum[blockIdx.x] = sh[0];
}

__global__ void k_scan_p2() {
    __shared__ int sh[1024];
    const int tid = threadIdx.x;
    const int v = (tid < SCAN_B) ? g_bsum[tid] : 0;
    sh[tid] = v;
    __syncthreads();
    for (int d = 1; d < 1024; d <<= 1) {
        int t = (tid >= d) ? sh[tid - d] : 0;
        __syncthreads();
        sh[tid] += t;
        __syncthreads();
    }
    if (tid < SCAN_B) g_bbase[tid] = sh[tid] - v;   // exclusive base
}

__global__ void k_scan_p3() {
    __shared__ int sh[SCAN_T];
    const int i = blockIdx.x * SCAN_T + threadIdx.x;
    const int v = (i < NN) ? g_deg[i] : 0;
    sh[threadIdx.x] = v;
    __syncthreads();
    for (int d = 1; d < SCAN_T; d <<= 1) {
        int t = (threadIdx.x >= d) ? sh[threadIdx.x - d] : 0;
        __syncthreads();
        sh[threadIdx.x] += t;
        __syncthreads();
    }
    const int incl = sh[threadIdx.x];
    const int base = g_bbase[blockIdx.x];
    if (i < NN) {
        const int off = base + incl - v;            // exclusive
        g_off[i] = off;
        g_cur[i] = off;
    }
    if (i == NN - 1) g_off[NN] = base + incl;       // == 2*NE
}

// ---------------------------------------------------------------------------
// CSR build: each undirected edge (u, i) inserts both directions.
// ---------------------------------------------------------------------------
__global__ void k_build(const int* __restrict__ eu, const int* __restrict__ ei) {
    int t = blockIdx.x * blockDim.x + threadIdx.x;
    if (t < NE) {
        const int u  = eu[t];
        const int it = NU + ei[t];
        const float w = g_dinv[u] * g_dinv[it];
        int pu = atomicAdd(&g_cur[u], 1);
        g_ent[pu] = Ent{it, w};
        int pi = atomicAdd(&g_cur[it], 1);
        g_ent[pi] = Ent{u, w};
    }
}

// ---------------------------------------------------------------------------
// TypeProjector (measured-good R5 version):
// out[row, :] = x[row, :128] @ W[128,32] + b.
// One warp per row; W staged in shared (16KB), row staged in shared (per-warp).
// LDS pattern per FMA step: 1 broadcast (xs) + 1 conflict-free (Ws).
// ---------------------------------------------------------------------------
__global__ void k_project(const float* __restrict__ x, const float* __restrict__ Wm,
                          const float* __restrict__ b, int row_offset, int rows) {
    __shared__ float Ws[IND * H];
    __shared__ float xs[8][IND];
    for (int i = threadIdx.x; i < IND * H; i += blockDim.x) Ws[i] = Wm[i];
    __syncthreads();

    const int warp = threadIdx.x >> 5;
    const int lane = threadIdx.x & 31;
    const float bias = b[lane];

    int row = blockIdx.x * 8 + warp;
    if (row < rows) {
        float4 v = reinterpret_cast<const float4*>(x + (size_t)row * IND)[lane];
        reinterpret_cast<float4*>(xs[warp])[lane] = v;
        __syncwarp();
        float acc = bias;
        #pragma unroll
        for (int k = 0; k < IND; k++)
            acc = fmaf(xs[warp][k], Ws[k * H + lane], acc);
        g_x0[(size_t)(row_offset + row) * H + lane] = acc;
    }
}

// ---------------------------------------------------------------------------
// Gather body: acc = sum_{j in [s,e)} ent[j].w * xin[ent[j].n * H + lane].
// Fully predicated 8-wide batches: no serial tail. Out-of-range slots read
// Ent{0, 0.0f} -> feature load hits the always-valid row 0 and the FMA adds
// exactly 0. Keeps MLP ~8 on the random 128B row loads for EVERY batch.
// ---------------------------------------------------------------------------
__device__ __forceinline__ float gather_row(const float* __restrict__ xin,
                                            int s, int e, int lane) {
    float acc = 0.0f;
    for (int j = s; j < e; j += 8) {
        Ent t[8];
        #pragma unroll
        for (int k = 0; k < 8; k++) {
            const int jj = j + k;
            t[k] = (jj < e) ? g_ent[jj] : Ent{0, 0.0f};
        }
        float v[8];
        #pragma unroll
        for (int k = 0; k < 8; k++)
            v[k] = xin[(size_t)t[k].n * H + lane];
        #pragma unroll
        for (int k = 0; k < 8; k++)
            acc = fmaf(t[k].w, v[k], acc);
    }
    return acc;
}

// Layer 1: x1[v] = sum_{n in N(v)} w * x0[n]. One warp per node, lane = column.
__global__ void __launch_bounds__(256) k_gather1() {
    const int v = blockIdx.x * (blockDim.x >> 5) + (threadIdx.x >> 5);
    if (v >= NN) return;
    const int lane = threadIdx.x & 31;
    const float acc = gather_row(g_x0, g_off[v], g_off[v + 1], lane);
    g_x1[(size_t)v * H + lane] = acc;
}

// Layer 2 + fused mean epilogue: out[v] = (x0[v] + x1[v] + gather(x1))/3.
__global__ void __launch_bounds__(256) k_gather2(float* __restrict__ out) {
    const int v = blockIdx.x * (blockDim.x >> 5) + (threadIdx.x >> 5);
    if (v >= NN) return;
    const int lane = threadIdx.x & 31;
    const float acc = gather_row(g_x1, g_off[v], g_off[v + 1], lane);
    const size_t idx = (size_t)v * H + lane;
    out[idx] = (g_x0[idx] + g_x1[idx] + acc) * (1.0f / 3.0f);
}

extern "C" void kernel_launch(void* const* d_in, const int* in_sizes, int n_in,
                              void* d_out, int out_size) {
    const float* x_user = (const float*)d_in[0];
    const float* x_item = (const float*)d_in[1];
    const int*   eu     = (const int*)  d_in[2];
    const int*   ei     = (const int*)  d_in[3];
    const float* Wu     = (const float*)d_in[4];
    const float* bu     = (const float*)d_in[5];
    const float* Wi     = (const float*)d_in[6];
    const float* bi     = (const float*)d_in[7];
    float* out = (float*)d_out;

    const int B = 256;

    // Launch order puts k_count_deg at captured idx 3 (projections are
    // independent of the graph preprocessing, so they slot in front).
    k_zero_deg<<<(NN + B - 1) / B, B>>>();                       // 0
    k_project<<<NU / 8, B>>>(x_user, Wu, bu, 0,  NU);            // 1
    k_project<<<NI / 8, B>>>(x_item, Wi, bi, NU, NI);            // 2
    k_count_deg<<<(NE + B - 1) / B, B>>>(eu, ei);                // 3 <- profiled
    k_scan_p1<<<SCAN_B, SCAN_T>>>();                             // 4 (+dinv)
    k_scan_p2<<<1, 1024>>>();                                    // 5
    k_scan_p3<<<SCAN_B, SCAN_T>>>();                             // 6
    k_build<<<(NE + B - 1) / B, B>>>(eu, ei);                    // 7

    const int warps_per_block = B / 32;
    const int gather_blocks = (NN + warps_per_block - 1) / warps_per_block;
    k_gather1<<<gather_blocks, B>>>();                           // 8
    k_gather2<<<gather_blocks, B>>>(out);                        // 9
}